// round 1
// baseline (speedup 1.0000x reference)
#include <cuda_runtime.h>

#define BB 4
#define NN 4096
#define FF 64
#define OO 64
#define K1 32   // blocks per batch, kernel1
#define K2 32   // blocks per batch, kernel2
#define K3 64   // blocks per batch, kernel3

// scratch (allocation-free rule: __device__ globals)
__device__ float g_srow[BB * NN];
__device__ float g_scol[BB * NN];
__device__ float g_Cpart[BB * K1];
__device__ float g_upart[BB * K2 * 128];

// Kernel 1: per-row dots s_col = x_row . w[0:64], s_row = x_row . w[64:128],
// plus per-block partial sum of s_col (for the degree constant C).
__global__ void k1_rowdots(const float* __restrict__ x,
                           const float* __restrict__ adj_w) {
    const int b    = blockIdx.y;
    const int blk  = blockIdx.x;
    const int warp = threadIdx.x >> 5;
    const int lane = threadIdx.x & 31;

    const float wc0 = adj_w[lane];
    const float wc1 = adj_w[lane + 32];
    const float wr0 = adj_w[64 + lane];
    const float wr1 = adj_w[96 + lane];

    const int rows_per_blk = NN / K1;      // 128
    const int row0 = blk * rows_per_blk;

    __shared__ float warp_sums[8];
    float scol_sum = 0.f;

    for (int r = warp; r < rows_per_blk; r += 8) {
        const int row = row0 + r;
        const float* xr = x + ((size_t)(b * NN + row) << 6);
        const float a = xr[lane];
        const float c = xr[lane + 32];
        float sc = a * wc0 + c * wc1;
        float sr = a * wr0 + c * wr1;
#pragma unroll
        for (int off = 16; off; off >>= 1) {
            sc += __shfl_xor_sync(0xffffffffu, sc, off);
            sr += __shfl_xor_sync(0xffffffffu, sr, off);
        }
        if (lane == 0) {
            g_srow[b * NN + row] = sr;
            g_scol[b * NN + row] = sc;
            scol_sum += sc;
        }
    }
    if (lane == 0) warp_sums[warp] = scol_sum;
    __syncthreads();
    if (threadIdx.x == 0) {
        float s = 0.f;
#pragma unroll
        for (int w = 0; w < 8; w++) s += warp_sums[w];
        g_Cpart[b * K1 + blk] = s;
    }
}

// Kernel 2: with C known, compute d[j] in closed form and accumulate per-block
// partials of u1[f] = sum_j d[j]*x[j,f] and u2[f] = sum_j s_col[j]*d[j]*x[j,f].
__global__ void k2_partials(const float* __restrict__ x,
                            const float* __restrict__ adj_b_p) {
    const int b   = blockIdx.y;
    const int blk = blockIdx.x;
    const int t   = threadIdx.x;      // 256 threads
    const int f   = t & 63;
    const int sub = t >> 6;           // 4 row-lanes

    __shared__ float sC;
    __shared__ float red[512];

    if (t == 0) {
        float s = 0.f;
        for (int k = 0; k < K1; k++) s += g_Cpart[b * K1 + k];
        sC = s;
    }
    __syncthreads();

    const float C  = sC;
    const float ab = *adj_b_p;
    const int rows_per_blk = NN / K2;  // 128
    const int row0 = blk * rows_per_blk;

    float acc1 = 0.f, acc2 = 0.f;
    for (int r = sub; r < rows_per_blk; r += 4) {
        const int bn = b * NN + row0 + r;
        const float sr = g_srow[bn];
        const float sc = g_scol[bn];
        const float d = rsqrtf(fmaxf(fmaf((float)NN, sr + ab, C), 1.0f));
        const float xv = x[((size_t)bn << 6) + f];
        acc1 = fmaf(d, xv, acc1);
        acc2 = fmaf(sc * d, xv, acc2);
    }
    red[t] = acc1;
    red[256 + t] = acc2;
    __syncthreads();
    if (t < 64) {
        const float s1 = red[t] + red[64 + t] + red[128 + t] + red[192 + t];
        const float s2 = red[256 + t] + red[320 + t] + red[384 + t] + red[448 + t];
        const int base = (b * K2 + blk) * 128;
        g_upart[base + t] = s1;
        g_upart[base + 64 + t] = s2;
    }
}

// Kernel 3: fold u-partials (L2-hot, tiny), matvec T1/T2 = u1/u2 @ W in shared,
// then stream the output: out[i,o] = relu(d[i]*((s_row[i]+ab)*T1[o] + T2[o]) + bias[o]).
__global__ void k3_output(const float* __restrict__ weight,
                          const float* __restrict__ bias,
                          const float* __restrict__ adj_b_p,
                          float* __restrict__ out) {
    const int b   = blockIdx.y;
    const int blk = blockIdx.x;
    const int t   = threadIdx.x;     // 256 threads

    __shared__ float su[128];
    __shared__ float sT[128];
    __shared__ float sC;

    if (t < 128) {
        float acc = 0.f;
        const int base = b * K2 * 128 + t;
#pragma unroll 4
        for (int k = 0; k < K2; k++) acc += g_upart[base + k * 128];
        su[t] = acc;
    }
    if (t == 255) {
        float s = 0.f;
        for (int k = 0; k < K1; k++) s += g_Cpart[b * K1 + k];
        sC = s;
    }
    __syncthreads();

    if (t < 128) {
        const int which = t >> 6;
        const int o = t & 63;
        const float* u = su + which * 64;
        float acc = 0.f;
#pragma unroll
        for (int ff = 0; ff < 64; ff++)
            acc = fmaf(u[ff], weight[ff * 64 + o], acc);
        sT[t] = acc;
    }
    __syncthreads();

    const int o   = t & 63;
    const int sub = t >> 6;
    const float T1 = sT[o];
    const float T2 = sT[64 + o];
    const float bv = bias[o];
    const float C  = sC;
    const float ab = *adj_b_p;

    const int rows_per_blk = NN / K3;   // 64
    const int row0 = blk * rows_per_blk;
    for (int r = sub; r < rows_per_blk; r += 4) {
        const int bn = b * NN + row0 + r;
        const float sr = g_srow[bn] + ab;
        const float d = rsqrtf(fmaxf(fmaf((float)NN, sr, C), 1.0f));
        const float v = d * fmaf(sr, T1, T2) + bv;
        out[((size_t)bn << 6) + o] = fmaxf(v, 0.f);
    }
}

extern "C" void kernel_launch(void* const* d_in, const int* in_sizes, int n_in,
                              void* d_out, int out_size) {
    // Map inputs by element count (all sizes are distinct): robust to ordering.
    const float* x = nullptr;       // 4*4096*64 = 1048576
    const float* adj_w = nullptr;   // 128
    const float* adj_b = nullptr;   // 1
    const float* weight = nullptr;  // 64*64 = 4096
    const float* bias = nullptr;    // 64
    for (int i = 0; i < n_in; i++) {
        switch (in_sizes[i]) {
            case 1048576: x      = (const float*)d_in[i]; break;
            case 128:     adj_w  = (const float*)d_in[i]; break;
            case 1:       adj_b  = (const float*)d_in[i]; break;
            case 4096:    weight = (const float*)d_in[i]; break;
            case 64:      bias   = (const float*)d_in[i]; break;
            default: break;
        }
    }
    float* out = (float*)d_out;

    dim3 g1(K1, BB), g2(K2, BB), g3(K3, BB);
    k1_rowdots<<<g1, 256>>>(x, adj_w);
    k2_partials<<<g2, 256>>>(x, adj_b);
    k3_output<<<g3, 256>>>(weight, bias, adj_b, out);
}

// round 2
// speedup vs baseline: 1.2845x; 1.2845x over previous
#include <cuda_runtime.h>

#define NN 4096
#define NROWS 16384           // BB*NN, rows of the flattened (B*N, F) matrix
#define GK1 256               // k1 blocks: 64 rows each
#define GK2 256               // k2 blocks: 64 rows each
#define GK3 128               // k3 blocks: 128 rows each

// scratch (allocation-free rule: __device__ globals)
__device__ float g_srow[NROWS];
__device__ float g_scol[NROWS];
__device__ float g_Cpart[GK1];          // per-k1-block partial of sum(s_col); 64 blocks per batch
__device__ float g_upart[GK2 * 128];    // per-k2-block partials of u1[64],u2[64]

// ---------------------------------------------------------------------------
// Kernel 1: s_col[row] = x[row,:].adj_w[0:64], s_row[row] = x[row,:].adj_w[64:128]
// 4 lanes per row, 4 independent float4 loads per thread (MLP=4).
// Also per-block partial sum of s_col for the degree constant C.
// ---------------------------------------------------------------------------
__global__ void k1_rowdots(const float4* __restrict__ x4,
                           const float4* __restrict__ w4) {
    const int t    = threadIdx.x;
    const int quad = t & 3;          // lane within row (covers 16 floats)
    const int row  = blockIdx.x * 64 + (t >> 2);

    float4 wc[4], wr[4], v[4];
#pragma unroll
    for (int i = 0; i < 4; i++) {
        wc[i] = w4[quad * 4 + i];
        wr[i] = w4[16 + quad * 4 + i];
    }
#pragma unroll
    for (int i = 0; i < 4; i++)
        v[i] = x4[row * 16 + quad * 4 + i];

    float sc = 0.f, sr = 0.f;
#pragma unroll
    for (int i = 0; i < 4; i++) {
        sc = fmaf(v[i].x, wc[i].x, fmaf(v[i].y, wc[i].y, fmaf(v[i].z, wc[i].z, fmaf(v[i].w, wc[i].w, sc))));
        sr = fmaf(v[i].x, wr[i].x, fmaf(v[i].y, wr[i].y, fmaf(v[i].z, wr[i].z, fmaf(v[i].w, wr[i].w, sr))));
    }
    // reduce across the 4 lanes of this row
    sc += __shfl_xor_sync(0xffffffffu, sc, 1);
    sc += __shfl_xor_sync(0xffffffffu, sc, 2);
    sr += __shfl_xor_sync(0xffffffffu, sr, 1);
    sr += __shfl_xor_sync(0xffffffffu, sr, 2);

    if (quad == 0) {
        g_srow[row] = sr;
        g_scol[row] = sc;
    }
    // block partial of sum(s_col): keep only one copy per row, then warp+block fold
    float p = (quad == 0) ? sc : 0.f;
    p += __shfl_xor_sync(0xffffffffu, p, 4);
    p += __shfl_xor_sync(0xffffffffu, p, 8);
    p += __shfl_xor_sync(0xffffffffu, p, 16);

    __shared__ float ws[8];
    if ((t & 31) == 0) ws[t >> 5] = p;
    __syncthreads();
    if (t == 0) {
        float s = 0.f;
#pragma unroll
        for (int w = 0; w < 8; w++) s += ws[w];
        g_Cpart[blockIdx.x] = s;
    }
}

// ---------------------------------------------------------------------------
// Kernel 2: with C known, d[j] = rsqrt(max(N*(s_row[j]+ab)+C, 1)).
// Per-block partials of u1[f] = sum_j d[j]*x[j,f], u2[f] = sum_j s_col[j]*d[j]*x[j,f].
// ---------------------------------------------------------------------------
__global__ void k2_partials(const float* __restrict__ x,
                            const float* __restrict__ adj_b_p) {
    const int t   = threadIdx.x;     // 256
    const int blk = blockIdx.x;
    const int b   = blk >> 6;        // 64 blocks per batch

    __shared__ float sC;
    if (t < 32) {                     // warp-parallel C fold (64 partials per batch)
        float p = g_Cpart[b * 64 + t] + g_Cpart[b * 64 + 32 + t];
        p += __shfl_xor_sync(0xffffffffu, p, 16);
        p += __shfl_xor_sync(0xffffffffu, p, 8);
        p += __shfl_xor_sync(0xffffffffu, p, 4);
        p += __shfl_xor_sync(0xffffffffu, p, 2);
        p += __shfl_xor_sync(0xffffffffu, p, 1);
        if (t == 0) sC = p;
    }
    __syncthreads();

    const float C  = sC;
    const float ab = *adj_b_p;
    const int f    = t & 63;
    const int sub  = t >> 6;
    const int row0 = blk * 64;

    float a1 = 0.f, a2 = 0.f;
#pragma unroll
    for (int r = sub; r < 64; r += 4) {
        const int row = row0 + r;
        const float srv = g_srow[row];
        const float scv = g_scol[row];
        const float d = rsqrtf(fmaxf(fmaf(4096.f, srv + ab, C), 1.0f));
        const float xv = x[(row << 6) + f];
        a1 = fmaf(d, xv, a1);
        a2 = fmaf(scv * d, xv, a2);
    }

    __shared__ float red[512];
    red[t] = a1;
    red[256 + t] = a2;
    __syncthreads();
    if (t < 64) {
        const float s1 = red[t] + red[64 + t] + red[128 + t] + red[192 + t];
        const float s2 = red[256 + t] + red[320 + t] + red[384 + t] + red[448 + t];
        g_upart[blk * 128 + t]      = s1;
        g_upart[blk * 128 + 64 + t] = s2;
    }
}

// ---------------------------------------------------------------------------
// Kernel 3: fold u-partials (L2-hot), T1/T2 = u1/u2 @ W, then stream output:
// out[i,o] = relu(d[i] * ((s_row[i]+ab)*T1[o] + T2[o]) + bias[o])
// ---------------------------------------------------------------------------
__global__ void k3_output(const float* __restrict__ weight,
                          const float* __restrict__ bias,
                          const float* __restrict__ adj_b_p,
                          float* __restrict__ out) {
    const int t   = threadIdx.x;     // 256
    const int blk = blockIdx.x;
    const int b   = blk >> 5;        // 32 blocks per batch

    __shared__ float su[128];
    __shared__ float sT[128];
    __shared__ float sC;

    if (t < 128) {                    // fold 64 u-partials per batch
        float acc = 0.f;
        const float* up = g_upart + b * 8192 + t;
#pragma unroll
        for (int k = 0; k < 64; k++) acc += up[k * 128];
        su[t] = acc;
    }
    if (t >= 224) {                   // warp 7: fold C
        const int l = t - 224;
        float p = g_Cpart[b * 64 + l] + g_Cpart[b * 64 + 32 + l];
        p += __shfl_xor_sync(0xffffffffu, p, 16);
        p += __shfl_xor_sync(0xffffffffu, p, 8);
        p += __shfl_xor_sync(0xffffffffu, p, 4);
        p += __shfl_xor_sync(0xffffffffu, p, 2);
        p += __shfl_xor_sync(0xffffffffu, p, 1);
        if (l == 0) sC = p;
    }
    __syncthreads();

    if (t < 128) {                    // matvec: T[which][o] = sum_f u[which][f]*W[f][o]
        const int which = t >> 6;
        const int o = t & 63;
        const float* u = su + which * 64;
        float acc = 0.f;
#pragma unroll
        for (int ff = 0; ff < 64; ff++)
            acc = fmaf(u[ff], weight[ff * 64 + o], acc);
        sT[t] = acc;
    }
    __syncthreads();

    const int o   = t & 63;
    const int sub = t >> 6;
    const float T1 = sT[o];
    const float T2 = sT[64 + o];
    const float bv = bias[o];
    const float C  = sC;
    const float ab = *adj_b_p;

    const int row0 = blk * 128;
#pragma unroll 4
    for (int r = sub; r < 128; r += 4) {
        const int row = row0 + r;
        const float srv = g_srow[row] + ab;
        const float d = rsqrtf(fmaxf(fmaf(4096.f, srv, C), 1.0f));
        const float v = d * fmaf(srv, T1, T2) + bv;
        out[(row << 6) + o] = fmaxf(v, 0.f);
    }
}

extern "C" void kernel_launch(void* const* d_in, const int* in_sizes, int n_in,
                              void* d_out, int out_size) {
    const float* x = nullptr;       // 1048576
    const float* adj_w = nullptr;   // 128
    const float* adj_b = nullptr;   // 1
    const float* weight = nullptr;  // 4096
    const float* bias = nullptr;    // 64
    for (int i = 0; i < n_in; i++) {
        switch (in_sizes[i]) {
            case 1048576: x      = (const float*)d_in[i]; break;
            case 128:     adj_w  = (const float*)d_in[i]; break;
            case 1:       adj_b  = (const float*)d_in[i]; break;
            case 4096:    weight = (const float*)d_in[i]; break;
            case 64:      bias   = (const float*)d_in[i]; break;
            default: break;
        }
    }
    float* out = (float*)d_out;

    k1_rowdots<<<GK1, 256>>>((const float4*)x, (const float4*)adj_w);
    k2_partials<<<GK2, 256>>>(x, adj_b);
    k3_output<<<GK3, 256>>>(weight, bias, adj_b, out);
}

// round 3
// speedup vs baseline: 1.5702x; 1.2225x over previous
#include <cuda_runtime.h>

#define GRID 128
#define TPB  512

// cross-block scratch (allocation-free rule: __device__ globals)
__device__ float g_Cpart[GRID];
__device__ float g_upart[GRID * 128];
__device__ float g_T[4 * 128];
__device__ unsigned g_cnt = 0;
__device__ volatile unsigned g_gen = 0;

// sense-reversal grid barrier: 128 CTAs are a single wave (<=148 SMs, 1 CTA/SM),
// so all blocks are co-resident and this cannot deadlock. Integer-only, deterministic.
__device__ __forceinline__ void gridbar() {
    __syncthreads();
    if (threadIdx.x == 0) {
        __threadfence();                       // release: make my block's writes visible
        unsigned g = g_gen;
        if (atomicAdd(&g_cnt, 1u) == GRID - 1) {
            g_cnt = 0;
            __threadfence();
            g_gen = g + 1;
        } else {
            while (g_gen == g) {}
        }
        __threadfence();                       // acquire
    }
    __syncthreads();
}

__device__ __forceinline__ float dot4(float4 a, float4 b, float acc) {
    return fmaf(a.x, b.x, fmaf(a.y, b.y, fmaf(a.z, b.z, fmaf(a.w, b.w, acc))));
}

__global__ void __launch_bounds__(TPB, 1)
gcn_fused(const float4* __restrict__ x4, const float* __restrict__ x,
          const float* __restrict__ adj_w,
          const float* __restrict__ adj_b_p,
          const float* __restrict__ weight,
          const float* __restrict__ bias,
          float* __restrict__ out) {
    const int t     = threadIdx.x;
    const int blk   = blockIdx.x;
    const int batch = blk >> 5;          // 32 blocks (4096 rows) per batch

    __shared__ float s_sr[128];          // per-block row dots (stay on-chip)
    __shared__ float s_sc[128];
    __shared__ float red[1024];
    __shared__ float ws[16];
    __shared__ float sCsh;

    // ---------------- Phase 1: row dots + per-block C partial -------------
    {
        const int quad = t & 3;          // 4 lanes per row (16 floats each)
        const int r    = t >> 2;         // 0..127
        const int row  = blk * 128 + r;

        const float4* w4 = (const float4*)adj_w;
        float4 wc0 = w4[quad * 4 + 0], wc1 = w4[quad * 4 + 1];
        float4 wc2 = w4[quad * 4 + 2], wc3 = w4[quad * 4 + 3];
        float4 wr0 = w4[16 + quad * 4 + 0], wr1 = w4[16 + quad * 4 + 1];
        float4 wr2 = w4[16 + quad * 4 + 2], wr3 = w4[16 + quad * 4 + 3];

        const float4* xr = x4 + (size_t)row * 16 + quad * 4;
        float4 v0 = xr[0], v1 = xr[1], v2 = xr[2], v3 = xr[3];

        float sc = dot4(v3, wc3, dot4(v2, wc2, dot4(v1, wc1, dot4(v0, wc0, 0.f))));
        float sr = dot4(v3, wr3, dot4(v2, wr2, dot4(v1, wr1, dot4(v0, wr0, 0.f))));
        sc += __shfl_xor_sync(0xffffffffu, sc, 1);
        sc += __shfl_xor_sync(0xffffffffu, sc, 2);
        sr += __shfl_xor_sync(0xffffffffu, sr, 1);
        sr += __shfl_xor_sync(0xffffffffu, sr, 2);

        if (quad == 0) { s_sr[r] = sr; s_sc[r] = sc; }

        float p = (quad == 0) ? sc : 0.f;      // one copy per row
        p += __shfl_xor_sync(0xffffffffu, p, 4);
        p += __shfl_xor_sync(0xffffffffu, p, 8);
        p += __shfl_xor_sync(0xffffffffu, p, 16);
        if ((t & 31) == 0) ws[t >> 5] = p;
        __syncthreads();
        if (t == 0) {
            float s = 0.f;
#pragma unroll
            for (int w = 0; w < 16; w++) s += ws[w];
            g_Cpart[blk] = s;
        }
    }
    gridbar();   // barrier 1: C partials visible

    // ---------------- Phase 2: u1/u2 partials (x reload hits L1) ----------
    float C, ab;
    {
        if (t < 32) {                    // per-batch C fold (32 partials)
            float p = __ldcg(&g_Cpart[batch * 32 + t]);
            p += __shfl_xor_sync(0xffffffffu, p, 16);
            p += __shfl_xor_sync(0xffffffffu, p, 8);
            p += __shfl_xor_sync(0xffffffffu, p, 4);
            p += __shfl_xor_sync(0xffffffffu, p, 2);
            p += __shfl_xor_sync(0xffffffffu, p, 1);
            if (t == 0) sCsh = p;
        }
        __syncthreads();
        C  = sCsh;
        ab = __ldg(adj_b_p);

        const int f   = t & 63;
        const int sub = t >> 6;          // 8 row-lanes
        float a1 = 0.f, a2 = 0.f;
#pragma unroll
        for (int k = 0; k < 16; k++) {
            const int r = sub + (k << 3);
            const float srv = s_sr[r];
            const float scv = s_sc[r];
            const float d = rsqrtf(fmaxf(fmaf(4096.f, srv + ab, C), 1.0f));
            const float xv = x[(size_t)((blk * 128 + r) << 6) + f];
            a1 = fmaf(d, xv, a1);
            a2 = fmaf(scv * d, xv, a2);
        }
        red[t] = a1;
        red[512 + t] = a2;
        __syncthreads();
        if (t < 64) {
            float s1 = 0.f, s2 = 0.f;
#pragma unroll
            for (int k = 0; k < 8; k++) {
                s1 += red[t + 64 * k];
                s2 += red[512 + t + 64 * k];
            }
            g_upart[blk * 128 + t]      = s1;
            g_upart[blk * 128 + 64 + t] = s2;
        }
    }
    gridbar();   // barrier 2: u partials visible

    // ---------------- Fold + matvec: 4 blocks, one per batch --------------
    if ((blk & 31) == 0) {
        const int e  = t & 127;
        const int g4 = t >> 7;           // 4 groups of 8 partials each
        float acc = 0.f;
#pragma unroll
        for (int k = 0; k < 8; k++)
            acc += __ldcg(&g_upart[(batch * 32 + g4 * 8 + k) * 128 + e]);
        red[t] = acc;
        __syncthreads();
        if (t < 128)
            red[512 + t] = red[t] + red[128 + t] + red[256 + t] + red[384 + t];
        __syncthreads();
        if (t < 128) {                   // T[which][o] = sum_f u[which][f] * W[f][o]
            const int which = t >> 6, o = t & 63;
            const float* u = &red[512 + which * 64];
            float acc2 = 0.f;
#pragma unroll
            for (int ff = 0; ff < 64; ff++)
                acc2 = fmaf(u[ff], weight[ff * 64 + o], acc2);
            g_T[batch * 128 + t] = acc2;
        }
    }
    gridbar();   // barrier 3: T visible

    // ---------------- Phase 3: stream output ------------------------------
    {
        const int o   = t & 63;
        const int sub = t >> 6;
        const float T1 = __ldcg(&g_T[batch * 128 + o]);
        const float T2 = __ldcg(&g_T[batch * 128 + 64 + o]);
        const float bv = bias[o];
#pragma unroll
        for (int k = 0; k < 16; k++) {
            const int r = sub + (k << 3);
            const float srv = s_sr[r] + ab;
            const float d = rsqrtf(fmaxf(fmaf(4096.f, srv, C), 1.0f));
            const float v = d * fmaf(srv, T1, T2) + bv;
            out[(size_t)((blk * 128 + r) << 6) + o] = fmaxf(v, 0.f);
        }
    }
}

extern "C" void kernel_launch(void* const* d_in, const int* in_sizes, int n_in,
                              void* d_out, int out_size) {
    const float* x = nullptr;       // 1048576
    const float* adj_w = nullptr;   // 128
    const float* adj_b = nullptr;   // 1
    const float* weight = nullptr;  // 4096
    const float* bias = nullptr;    // 64
    for (int i = 0; i < n_in; i++) {
        switch (in_sizes[i]) {
            case 1048576: x      = (const float*)d_in[i]; break;
            case 128:     adj_w  = (const float*)d_in[i]; break;
            case 1:       adj_b  = (const float*)d_in[i]; break;
            case 4096:    weight = (const float*)d_in[i]; break;
            case 64:      bias   = (const float*)d_in[i]; break;
            default: break;
        }
    }
    float* out = (float*)d_out;

    gcn_fused<<<GRID, TPB>>>((const float4*)x, x, adj_w, adj_b, weight, bias, out);
}

// round 4
// speedup vs baseline: 1.8221x; 1.1604x over previous
#include <cuda_runtime.h>

#define GRID 128
#define TPB  512

// cross-block scratch (allocation-free rule: __device__ globals)
__device__ float g_Cpart[GRID];
__device__ float g_upart[GRID * 128];
__device__ unsigned g_cnt = 0;
__device__ unsigned g_gen = 0;

// Grid barrier with scoped release/acquire (no full __threadfence -> no CCTL.IVALL
// L1D flush). 128 CTAs of 512 threads = single wave (<=148 SMs), so all blocks are
// co-resident: spin cannot deadlock. Counters never feed the output (deterministic).
__device__ __forceinline__ void gridbar() {
    __syncthreads();
    if (threadIdx.x == 0) {
        unsigned g;
        asm volatile("ld.relaxed.gpu.global.u32 %0, [%1];" : "=r"(g) : "l"(&g_gen));
        unsigned old;
        asm volatile("atom.acq_rel.gpu.global.add.u32 %0, [%1], %2;"
                     : "=r"(old) : "l"(&g_cnt), "r"(1u) : "memory");
        if (old == GRID - 1) {
            asm volatile("st.relaxed.gpu.global.u32 [%0], %1;" :: "l"(&g_cnt), "r"(0u) : "memory");
            asm volatile("st.release.gpu.global.u32 [%0], %1;" :: "l"(&g_gen), "r"(g + 1) : "memory");
        } else {
            unsigned cur;
            do {
                asm volatile("ld.acquire.gpu.global.u32 %0, [%1];"
                             : "=r"(cur) : "l"(&g_gen) : "memory");
            } while (cur == g);
        }
    }
    __syncthreads();
}

__device__ __forceinline__ float dot4(float4 a, float4 b, float acc) {
    return fmaf(a.x, b.x, fmaf(a.y, b.y, fmaf(a.z, b.z, fmaf(a.w, b.w, acc))));
}

__global__ void __launch_bounds__(TPB, 1)
gcn_fused(const float4* __restrict__ x4,
          const float* __restrict__ adj_w,
          const float* __restrict__ adj_b_p,
          const float* __restrict__ weight,
          const float* __restrict__ bias,
          float* __restrict__ out) {
    const int t     = threadIdx.x;
    const int blk   = blockIdx.x;
    const int batch = blk >> 5;          // 32 blocks (4096 rows) per batch

    __shared__ float sx[128 * 64];       // this block's x tile (32 KB) - loaded ONCE
    __shared__ float s_sr[128];
    __shared__ float s_sc[128];
    __shared__ float red[1024];
    __shared__ float sT[128];
    __shared__ float ws[16];
    __shared__ float sCsh;

    // ---------- Phase 1: load x tile -> smem, row dots, C partial ----------
    {
        const int quad = t & 3;          // 4 lanes per row (16 floats each)
        const int r    = t >> 2;         // 0..127
        const int row  = blk * 128 + r;

        const float4* w4 = (const float4*)adj_w;
        float4 wc0 = w4[quad * 4 + 0], wc1 = w4[quad * 4 + 1];
        float4 wc2 = w4[quad * 4 + 2], wc3 = w4[quad * 4 + 3];
        float4 wr0 = w4[16 + quad * 4 + 0], wr1 = w4[16 + quad * 4 + 1];
        float4 wr2 = w4[16 + quad * 4 + 2], wr3 = w4[16 + quad * 4 + 3];

        const float4* xr = x4 + (size_t)row * 16 + quad * 4;
        float4 v0 = xr[0], v1 = xr[1], v2 = xr[2], v3 = xr[3];

        float4* sxr = (float4*)(sx + r * 64 + quad * 16);
        sxr[0] = v0; sxr[1] = v1; sxr[2] = v2; sxr[3] = v3;

        float sc = dot4(v3, wc3, dot4(v2, wc2, dot4(v1, wc1, dot4(v0, wc0, 0.f))));
        float sr = dot4(v3, wr3, dot4(v2, wr2, dot4(v1, wr1, dot4(v0, wr0, 0.f))));
        sc += __shfl_xor_sync(0xffffffffu, sc, 1);
        sc += __shfl_xor_sync(0xffffffffu, sc, 2);
        sr += __shfl_xor_sync(0xffffffffu, sr, 1);
        sr += __shfl_xor_sync(0xffffffffu, sr, 2);

        if (quad == 0) { s_sr[r] = sr; s_sc[r] = sc; }

        float p = (quad == 0) ? sc : 0.f;
        p += __shfl_xor_sync(0xffffffffu, p, 4);
        p += __shfl_xor_sync(0xffffffffu, p, 8);
        p += __shfl_xor_sync(0xffffffffu, p, 16);
        if ((t & 31) == 0) ws[t >> 5] = p;
        __syncthreads();
        if (t == 0) {
            float s = 0.f;
#pragma unroll
            for (int w = 0; w < 16; w++) s += ws[w];
            __stcg(&g_Cpart[blk], s);
        }
    }
    gridbar();   // barrier 1: C partials visible in L2

    // ---------- Phase 2: fold C, u1/u2 partials (x from smem) --------------
    float C, ab;
    {
        if (t < 32) {                    // per-batch C fold (32 partials)
            float p = __ldcg(&g_Cpart[batch * 32 + t]);
            p += __shfl_xor_sync(0xffffffffu, p, 16);
            p += __shfl_xor_sync(0xffffffffu, p, 8);
            p += __shfl_xor_sync(0xffffffffu, p, 4);
            p += __shfl_xor_sync(0xffffffffu, p, 2);
            p += __shfl_xor_sync(0xffffffffu, p, 1);
            if (t == 0) sCsh = p;
        }
        __syncthreads();
        C  = sCsh;
        ab = __ldg(adj_b_p);

        const int f   = t & 63;
        const int sub = t >> 6;          // 8 row-lanes
        float a1 = 0.f, a2 = 0.f;
#pragma unroll
        for (int k = 0; k < 16; k++) {
            const int r = sub + (k << 3);
            const float srv = s_sr[r];
            const float scv = s_sc[r];
            const float d = rsqrtf(fmaxf(fmaf(4096.f, srv + ab, C), 1.0f));
            const float xv = sx[r * 64 + f];
            a1 = fmaf(d, xv, a1);
            a2 = fmaf(scv * d, xv, a2);
        }
        red[t] = a1;
        red[512 + t] = a2;
        __syncthreads();
        if (t < 64) {
            float s1 = 0.f, s2 = 0.f;
#pragma unroll
            for (int k = 0; k < 8; k++) {
                s1 += red[t + 64 * k];
                s2 += red[512 + t + 64 * k];
            }
            __stcg(&g_upart[blk * 128 + t],      s1);
            __stcg(&g_upart[blk * 128 + 64 + t], s2);
        }
    }
    gridbar();   // barrier 2: u partials visible in L2

    // ---------- Phase 3: every block folds u + matvec T, streams output ----
    {
        // fold 32 u-partials of this batch: 4096 floats, 8 ldcg per thread
        const int e  = t & 127;
        const int g4 = t >> 7;           // 4 groups of 8 partials
        float acc = 0.f;
#pragma unroll
        for (int k = 0; k < 8; k++)
            acc += __ldcg(&g_upart[(batch * 32 + g4 * 8 + k) * 128 + e]);
        red[t] = acc;
        __syncthreads();
        if (t < 128) {
            const float u = red[t] + red[128 + t] + red[256 + t] + red[384 + t];
            red[512 + t] = u;
        }
        __syncthreads();
        if (t < 128) {                   // T[which][o] = sum_f u[which][f] * W[f][o]
            const int which = t >> 6, o = t & 63;
            const float* u = &red[512 + which * 64];
            float acc2 = 0.f;
#pragma unroll
            for (int ff = 0; ff < 64; ff++)
                acc2 = fmaf(u[ff], weight[ff * 64 + o], acc2);
            sT[t] = acc2;
        }
        __syncthreads();

        const int o   = t & 63;
        const int sub = t >> 6;
        const float T1 = sT[o];
        const float T2 = sT[64 + o];
        const float bv = bias[o];
#pragma unroll
        for (int k = 0; k < 16; k++) {
            const int r = sub + (k << 3);
            const float srv = s_sr[r] + ab;
            const float d = rsqrtf(fmaxf(fmaf(4096.f, srv, C), 1.0f));
            const float v = d * fmaf(srv, T1, T2) + bv;
            out[(size_t)((blk * 128 + r) << 6) + o] = fmaxf(v, 0.f);
        }
    }
}

extern "C" void kernel_launch(void* const* d_in, const int* in_sizes, int n_in,
                              void* d_out, int out_size) {
    const float* x = nullptr;       // 1048576
    const float* adj_w = nullptr;   // 128
    const float* adj_b = nullptr;   // 1
    const float* weight = nullptr;  // 4096
    const float* bias = nullptr;    // 64
    for (int i = 0; i < n_in; i++) {
        switch (in_sizes[i]) {
            case 1048576: x      = (const float*)d_in[i]; break;
            case 128:     adj_w  = (const float*)d_in[i]; break;
            case 1:       adj_b  = (const float*)d_in[i]; break;
            case 4096:    weight = (const float*)d_in[i]; break;
            case 64:      bias   = (const float*)d_in[i]; break;
            default: break;
        }
    }
    float* out = (float*)d_out;

    gcn_fused<<<GRID, TPB>>>((const float4*)x, adj_w, adj_b, weight, bias, out);
}